// round 5
// baseline (speedup 1.0000x reference)
#include <cuda_runtime.h>
#include <cuda_bf16.h>
#include <cstdint>
#include <math.h>

// Problem constants
constexpr int NB  = 4;     // batch
constexpr int NN  = 2048;  // nodes
constexpr int IND = 256;   // in_dim
constexpr int NH  = 4;     // heads
constexpr int OD  = 64;    // out_dim per head
constexpr int OUT_ELEMS = NB * NN * IND;
// d_out layout: [out (B,N,H*OD)] then [b_inv (B,H,N,N)]

// Scratch
__device__ float g_pre[(size_t)NB * NN * 512];              // gate [0,256) + h [256,512)
__device__ __nv_bfloat16 g_BT_hi[512 * IND];                // B^T for k_pre: [j][k]
__device__ __nv_bfloat16 g_BT_lo[512 * IND];

// ====================== helpers ======================
__device__ __forceinline__ uint32_t smem_to_u32(const void* p) {
    uint32_t a;
    asm("{ .reg .u64 t; cvta.to.shared.u64 t, %1; cvt.u32.u64 %0, t; }" : "=r"(a) : "l"(p));
    return a;
}
__device__ __forceinline__ void split2(float x0, float x1, uint32_t& hi, uint32_t& lo) {
    __nv_bfloat16 h0 = __float2bfloat16(x0), h1 = __float2bfloat16(x1);
    hi = (uint32_t)__bfloat16_as_ushort(h0) | ((uint32_t)__bfloat16_as_ushort(h1) << 16);
    float r0 = x0 - __bfloat162float(h0), r1 = x1 - __bfloat162float(h1);
    __nv_bfloat16 l0 = __float2bfloat16(r0), l1 = __float2bfloat16(r1);
    lo = (uint32_t)__bfloat16_as_ushort(l0) | ((uint32_t)__bfloat16_as_ushort(l1) << 16);
}
__device__ __forceinline__ void ldsm_x4(uint32_t r[4], uint32_t addr) {
    asm volatile("ldmatrix.sync.aligned.m8n8.x4.shared.b16 {%0,%1,%2,%3}, [%4];"
        : "=r"(r[0]), "=r"(r[1]), "=r"(r[2]), "=r"(r[3]) : "r"(addr));
}
__device__ __forceinline__ void ldsm_x4t(uint32_t r[4], uint32_t addr) {
    asm volatile("ldmatrix.sync.aligned.m8n8.x4.trans.shared.b16 {%0,%1,%2,%3}, [%4];"
        : "=r"(r[0]), "=r"(r[1]), "=r"(r[2]), "=r"(r[3]) : "r"(addr));
}
__device__ __forceinline__ void mma_bf16(float c[4], const uint32_t a[4], uint32_t b0, uint32_t b1) {
    asm volatile("mma.sync.aligned.m16n8k16.row.col.f32.bf16.bf16.f32 "
        "{%0,%1,%2,%3}, {%4,%5,%6,%7}, {%8,%9}, {%0,%1,%2,%3};"
        : "+f"(c[0]), "+f"(c[1]), "+f"(c[2]), "+f"(c[3])
        : "r"(a[0]), "r"(a[1]), "r"(a[2]), "r"(a[3]), "r"(b0), "r"(b1));
}
#define SWZ128(b) ((b) ^ (((b) >> 3) & 0x70))
#define SWZ64(b)  ((b) ^ (((b) >> 3) & 0x30))

// =====================================================================
// Prep: build B^T (bf16 hi/lo) for k_pre.  j<256: Hw[j][k]; j>=256: W[h][k][o]
// =====================================================================
__global__ void k_prep(const float* __restrict__ Hw, const float* __restrict__ W)
{
    const int j = blockIdx.x;
    const int k = threadIdx.x;
    float v;
    if (j < 256) v = Hw[(size_t)j * IND + k];
    else {
        int jj = j - 256, h = jj >> 6, o = jj & 63;
        v = W[((size_t)h * IND + k) * OD + o];
    }
    __nv_bfloat16 hi = __float2bfloat16(v);
    __nv_bfloat16 lo = __float2bfloat16(v - __bfloat162float(hi));
    g_BT_hi[(size_t)j * IND + k] = hi;
    g_BT_lo[(size_t)j * IND + k] = lo;
}

// =====================================================================
// Kernel 1: HMMA pre-GEMM  C[8192,512] = feat[8192,256] @ BT^T
// (unchanged from R4 — passed)
// =====================================================================
constexpr int STAGE_PRE = 24576;
constexpr int SMEM_PRE = 2 * STAGE_PRE + 128;

__global__ __launch_bounds__(256, 2) void k_pre(
    const float* __restrict__ feat, const float* __restrict__ Hb)
{
    extern __shared__ char dsm_raw[];
    char* sm = (char*)(((uintptr_t)dsm_raw + 127) & ~(uintptr_t)127);
    const uint32_t smu = smem_to_u32(sm);

    const int tid = threadIdx.x;
    const int lane = tid & 31, wid = tid >> 5;
    const int r0 = blockIdx.x * 128;
    const int j0 = blockIdx.y * 64;

    const float* A = feat + (size_t)r0 * IND;

    const int arow = tid >> 3;
    const int acol = (tid & 7) << 2;
    const int brow = tid >> 2;
    const int bk8  = (tid & 3) << 3;

    uint32_t saoff[4];
#pragma unroll
    for (int j = 0; j < 4; j++)
        saoff[j] = SWZ64((uint32_t)(arow + 32 * j) * 64 + (uint32_t)acol * 2);
    const uint32_t sboff = SWZ64((uint32_t)brow * 64 + (uint32_t)bk8 * 2);

    float4 ar[4];
    uint4 bhr, blr;
#pragma unroll
    for (int j = 0; j < 4; j++)
        ar[j] = *(const float4*)&A[(size_t)(arow + 32 * j) * IND + acol];
    bhr = *(const uint4*)&g_BT_hi[(size_t)(j0 + brow) * IND + bk8];
    blr = *(const uint4*)&g_BT_lo[(size_t)(j0 + brow) * IND + bk8];

    float acc[2][4][4];
#pragma unroll
    for (int mi = 0; mi < 2; mi++)
#pragma unroll
        for (int ni = 0; ni < 4; ni++)
#pragma unroll
            for (int r = 0; r < 4; r++) acc[mi][ni][r] = 0.0f;

    const int m_w = (wid >> 1) * 32;
    const int n_w = (wid & 1) * 32;
    const int a_row_l = lane & 15;
    const int a_colb  = ((lane >> 4) << 3) * 2;
    const int b_row_l = (lane & 7) + ((lane >> 4) << 3);
    const int b_kb    = (((lane >> 3) & 1) << 4);

    for (int c = 0; c < 8; c++) {
        char* buf = sm + (c & 1) * STAGE_PRE;
        const uint32_t bufu = smu + (c & 1) * STAGE_PRE;
        const int k0 = c * 32;

        __syncthreads();
#pragma unroll
        for (int j = 0; j < 4; j++) {
            uint32_t h0, l0, h1, l1;
            split2(ar[j].x, ar[j].y, h0, l0);
            split2(ar[j].z, ar[j].w, h1, l1);
            *(uint2*)(buf + saoff[j])        = make_uint2(h0, h1);
            *(uint2*)(buf + 8192 + saoff[j]) = make_uint2(l0, l1);
        }
        *(uint4*)(buf + 16384 + sboff) = bhr;
        *(uint4*)(buf + 20480 + sboff) = blr;
        __syncthreads();

        if (c < 7) {
            const int kn = k0 + 32;
#pragma unroll
            for (int j = 0; j < 4; j++)
                ar[j] = *(const float4*)&A[(size_t)(arow + 32 * j) * IND + kn + acol];
            bhr = *(const uint4*)&g_BT_hi[(size_t)(j0 + brow) * IND + kn + bk8];
            blr = *(const uint4*)&g_BT_lo[(size_t)(j0 + brow) * IND + kn + bk8];
        }

#pragma unroll
        for (int ks = 0; ks < 2; ks++) {
            uint32_t ah[2][4], al[2][4], bhf[2][4], blf[2][4];
#pragma unroll
            for (int mi = 0; mi < 2; mi++) {
                uint32_t sw = SWZ64((uint32_t)(m_w + mi * 16 + a_row_l) * 64 + (uint32_t)(ks * 32) + a_colb);
                ldsm_x4(ah[mi], bufu + sw);
                ldsm_x4(al[mi], bufu + 8192 + sw);
            }
#pragma unroll
            for (int nj = 0; nj < 2; nj++) {
                uint32_t sw = SWZ64((uint32_t)(n_w + nj * 16 + b_row_l) * 64 + (uint32_t)(ks * 32) + b_kb);
                ldsm_x4(bhf[nj], bufu + 16384 + sw);
                ldsm_x4(blf[nj], bufu + 20480 + sw);
            }
#pragma unroll
            for (int mi = 0; mi < 2; mi++)
#pragma unroll
                for (int ni = 0; ni < 4; ni++) {
                    const int j = ni >> 1, p = (ni & 1) << 1;
                    mma_bf16(acc[mi][ni], ah[mi], bhf[j][p], bhf[j][p + 1]);
                    mma_bf16(acc[mi][ni], ah[mi], blf[j][p], blf[j][p + 1]);
                    mma_bf16(acc[mi][ni], al[mi], bhf[j][p], bhf[j][p + 1]);
                }
        }
    }

    const bool is_gate = (j0 < 256);
#pragma unroll
    for (int mi = 0; mi < 2; mi++) {
#pragma unroll
        for (int rr = 0; rr < 2; rr++) {
            const int m = r0 + m_w + mi * 16 + (lane >> 2) + rr * 8;
#pragma unroll
            for (int ni = 0; ni < 4; ni++) {
                const int j = j0 + n_w + ni * 8 + ((lane & 3) << 1);
                float v0 = acc[mi][ni][rr * 2 + 0];
                float v1 = acc[mi][ni][rr * 2 + 1];
                if (is_gate) {
                    v0 = 1.0f / (1.0f + expf(-(v0 + __ldg(&Hb[j]))));
                    v1 = 1.0f / (1.0f + expf(-(v1 + __ldg(&Hb[j + 1]))));
                }
                *(float2*)&g_pre[(size_t)m * 512 + j] = make_float2(v0, v1);
            }
        }
    }
}

// =====================================================================
// Kernel 2 (v5): HMMA main GEMM per (b,h): C[2048,64] = IB @ h
//   A NEVER touches SMEM: each warp owns 16 unique M-rows, loads A
//   fragments directly from GMEM (LDG.64, mma layout), splits to bf16
//   hi/lo in registers, write-through b_inv copy as STG.64 (.cs hints).
//   Only B (32x64 per chunk) is staged in double-buffered SMEM.
//   Warp tile 16x64, acc[8][4]. K-chunk 32, 64 chunks.
// =====================================================================
constexpr int SMEM_MAIN = 2 * 8192 + 128;

__global__ __launch_bounds__(256, 2) void k_main_mma(
    const float* __restrict__ IB, const float* __restrict__ feat,
    const float* __restrict__ bias, float* __restrict__ out)
{
    extern __shared__ char dsm_raw[];
    char* sm = (char*)(((uintptr_t)dsm_raw + 127) & ~(uintptr_t)127);
    const uint32_t smu = smem_to_u32(sm);

    const int tid = threadIdx.x;
    const int lane = tid & 31, wid = tid >> 5;
    const int r0 = blockIdx.x * 128;
    const int bh = blockIdx.y, bb = bh >> 2, hh = bh & 3;

    const float* A   = IB + (size_t)bh * NN * NN + (size_t)r0 * NN;
    float* Acopy     = out + OUT_ELEMS + (size_t)bh * NN * NN + (size_t)r0 * NN;
    const float* Bsrc = g_pre + (size_t)bb * NN * 512 + 256 + hh * 64;  // [k][o] stride 512

    // --- B staging map (all 256 threads) ---
    const int brow = tid >> 3;            // k row 0..31
    const int bcol = (tid & 7) << 3;      // o col base (8 floats)
    const uint32_t sboff = SWZ128((uint32_t)brow * 128 + (uint32_t)bcol * 2);

    // --- A direct-fragment addressing ---
    const int g  = lane >> 2;             // row group 0..7
    const int t2 = (lane & 3) << 1;       // col pair base
    const int m_w = wid * 16;
    const float* pA0 = A + (size_t)(m_w + g) * NN;
    const float* pA1 = pA0 + 8 * NN;
    float* pC0 = Acopy + (size_t)(m_w + g) * NN;
    float* pC1 = pC0 + 8 * NN;

    // --- ldsm B lane addressing ---
    const int b_krow = (lane & 7) + ((lane >> 3) & 1) * 8;
    const int b_ncol = (lane >> 4) << 3;

    float acc[8][4];
#pragma unroll
    for (int ni = 0; ni < 8; ni++)
#pragma unroll
        for (int r = 0; r < 4; r++) acc[ni][r] = 0.0f;

    // prefetch chunk 0
    float4 br0 = __ldg((const float4*)&Bsrc[(size_t)brow * 512 + bcol]);
    float4 br1 = __ldg((const float4*)&Bsrc[(size_t)brow * 512 + bcol + 4]);
    float2 a2[8];
#pragma unroll
    for (int ks = 0; ks < 2; ks++) {
        const int kb = ks * 16 + t2;
        a2[ks * 4 + 0] = __ldcs((const float2*)&pA0[kb]);
        a2[ks * 4 + 1] = __ldcs((const float2*)&pA1[kb]);
        a2[ks * 4 + 2] = __ldcs((const float2*)&pA0[kb + 8]);
        a2[ks * 4 + 3] = __ldcs((const float2*)&pA1[kb + 8]);
    }

    for (int c = 0; c < 64; c++) {
        char* buf = sm + (c & 1) * 8192;
        const uint32_t bufu = smu + (c & 1) * 8192;
        const int k0 = c * 32;

        __syncthreads();
        // stage B (split to hi/lo)
        {
            uint32_t h0, l0, h1, l1, h2, l2, h3, l3;
            split2(br0.x, br0.y, h0, l0);
            split2(br0.z, br0.w, h1, l1);
            split2(br1.x, br1.y, h2, l2);
            split2(br1.z, br1.w, h3, l3);
            *(uint4*)(buf + sboff)        = make_uint4(h0, h1, h2, h3);
            *(uint4*)(buf + 4096 + sboff) = make_uint4(l0, l1, l2, l3);
        }
        __syncthreads();

        // prefetch next B
        if (c < 63) {
            const int kn = k0 + 32;
            br0 = __ldg((const float4*)&Bsrc[(size_t)(kn + brow) * 512 + bcol]);
            br1 = __ldg((const float4*)&Bsrc[(size_t)(kn + brow) * 512 + bcol + 4]);
        }

        // A: write-through copy + split to fragments
        uint32_t ah[2][4], al[2][4];
#pragma unroll
        for (int ks = 0; ks < 2; ks++) {
            const int kb = k0 + ks * 16 + t2;
            __stcs((float2*)&pC0[kb],     a2[ks * 4 + 0]);
            __stcs((float2*)&pC1[kb],     a2[ks * 4 + 1]);
            __stcs((float2*)&pC0[kb + 8], a2[ks * 4 + 2]);
            __stcs((float2*)&pC1[kb + 8], a2[ks * 4 + 3]);
            split2(a2[ks * 4 + 0].x, a2[ks * 4 + 0].y, ah[ks][0], al[ks][0]);
            split2(a2[ks * 4 + 1].x, a2[ks * 4 + 1].y, ah[ks][1], al[ks][1]);
            split2(a2[ks * 4 + 2].x, a2[ks * 4 + 2].y, ah[ks][2], al[ks][2]);
            split2(a2[ks * 4 + 3].x, a2[ks * 4 + 3].y, ah[ks][3], al[ks][3]);
        }
        // prefetch next A
        if (c < 63) {
            const int kn = k0 + 32;
#pragma unroll
            for (int ks = 0; ks < 2; ks++) {
                const int kb = kn + ks * 16 + t2;
                a2[ks * 4 + 0] = __ldcs((const float2*)&pA0[kb]);
                a2[ks * 4 + 1] = __ldcs((const float2*)&pA1[kb]);
                a2[ks * 4 + 2] = __ldcs((const float2*)&pA0[kb + 8]);
                a2[ks * 4 + 3] = __ldcs((const float2*)&pA1[kb + 8]);
            }
        }

        // compute: 2 k16 steps, full n=64 per warp
#pragma unroll
        for (int ks = 0; ks < 2; ks++) {
            uint32_t bhf[4][4], blf[4][4];
#pragma unroll
            for (int nj = 0; nj < 4; nj++) {
                uint32_t sw = SWZ128((uint32_t)(ks * 16 + b_krow) * 128 + (uint32_t)(nj * 16 + b_ncol) * 2);
                ldsm_x4t(bhf[nj], bufu + sw);
                ldsm_x4t(blf[nj], bufu + 4096 + sw);
            }
#pragma unroll
            for (int ni = 0; ni < 8; ni++) {
                const int j = ni >> 1, p = (ni & 1) << 1;
                mma_bf16(acc[ni], ah[ks], bhf[j][p], bhf[j][p + 1]);
                mma_bf16(acc[ni], ah[ks], blf[j][p], blf[j][p + 1]);
                mma_bf16(acc[ni], al[ks], bhf[j][p], bhf[j][p + 1]);
            }
        }
    }

    // epilogue: bias + elu + sigmoid-gate blend
#pragma unroll
    for (int rr = 0; rr < 2; rr++) {
        const int nrow = r0 + m_w + g + rr * 8;
        const size_t row = (size_t)bb * NN + nrow;
#pragma unroll
        for (int ni = 0; ni < 8; ni++) {
            const int col = ni * 8 + t2;
            const int cg = hh * 64 + col;
            float v0 = acc[ni][rr * 2 + 0] + __ldg(&bias[col]);
            float v1 = acc[ni][rr * 2 + 1] + __ldg(&bias[col + 1]);
            float e0 = (v0 > 0.0f) ? v0 : expm1f(v0);
            float e1 = (v1 > 0.0f) ? v1 : expm1f(v1);
            float2 g2 = *(const float2*)&g_pre[row * 512 + cg];
            float2 f2 = *(const float2*)&feat[row * IND + cg];
            float2 o2;
            o2.x = g2.x * e0 + (1.0f - g2.x) * f2.x;
            o2.y = g2.y * e1 + (1.0f - g2.y) * f2.y;
            *(float2*)&out[row * IND + cg] = o2;
        }
    }
}

extern "C" void kernel_launch(void* const* d_in, const int* in_sizes, int n_in,
                              void* d_out, int out_size)
{
    const float* feat = (const float*)d_in[0];  // [4,2048,256]
    const float* IB   = (const float*)d_in[1];  // [4,4,2048,2048]
    const float* W    = (const float*)d_in[2];  // [4,256,64]
    const float* bias = (const float*)d_in[3];  // [64]
    const float* Hw   = (const float*)d_in[4];  // [256,256]
    const float* Hb   = (const float*)d_in[5];  // [256]
    float* out = (float*)d_out;

    // Prep: bf16 hi/lo B^T for k_pre
    k_prep<<<512, 256>>>(Hw, W);

    // Kernel 1: gate + h (HMMA)
    cudaFuncSetAttribute(k_pre, cudaFuncAttributeMaxDynamicSharedMemorySize, SMEM_PRE);
    dim3 g1(NB * NN / 128, 512 / 64);
    k_pre<<<g1, 256, SMEM_PRE>>>(feat, Hb);

    // Kernel 2: HMMA main GEMM (A direct from GMEM) + IB copy + fused epilogue
    cudaFuncSetAttribute(k_main_mma, cudaFuncAttributeMaxDynamicSharedMemorySize, SMEM_MAIN);
    dim3 g2(NN / 128, NB * NH);
    k_main_mma<<<g2, 256, SMEM_MAIN>>>(IB, feat, bias, out);
}

// round 6
// speedup vs baseline: 1.2334x; 1.2334x over previous
#include <cuda_runtime.h>
#include <cuda_bf16.h>
#include <cstdint>
#include <math.h>

// Problem constants
constexpr int NB  = 4;     // batch
constexpr int NN  = 2048;  // nodes
constexpr int IND = 256;   // in_dim
constexpr int NH  = 4;     // heads
constexpr int OD  = 64;    // out_dim per head
constexpr int OUT_ELEMS = NB * NN * IND;
// d_out layout: [out (B,N,H*OD)] then [b_inv (B,H,N,N)]

// Scratch
__device__ float g_pre[(size_t)NB * NN * 512];              // gate [0,256) + h [256,512)
__device__ __nv_bfloat16 g_BT_hi[512 * IND];                // B^T for k_pre: [j][k]
__device__ __nv_bfloat16 g_BT_lo[512 * IND];

// ====================== helpers ======================
__device__ __forceinline__ uint32_t smem_to_u32(const void* p) {
    uint32_t a;
    asm("{ .reg .u64 t; cvta.to.shared.u64 t, %1; cvt.u32.u64 %0, t; }" : "=r"(a) : "l"(p));
    return a;
}
__device__ __forceinline__ void split2(float x0, float x1, uint32_t& hi, uint32_t& lo) {
    __nv_bfloat16 h0 = __float2bfloat16(x0), h1 = __float2bfloat16(x1);
    hi = (uint32_t)__bfloat16_as_ushort(h0) | ((uint32_t)__bfloat16_as_ushort(h1) << 16);
    float r0 = x0 - __bfloat162float(h0), r1 = x1 - __bfloat162float(h1);
    __nv_bfloat16 l0 = __float2bfloat16(r0), l1 = __float2bfloat16(r1);
    lo = (uint32_t)__bfloat16_as_ushort(l0) | ((uint32_t)__bfloat16_as_ushort(l1) << 16);
}
__device__ __forceinline__ void ldsm_x4(uint32_t r[4], uint32_t addr) {
    asm volatile("ldmatrix.sync.aligned.m8n8.x4.shared.b16 {%0,%1,%2,%3}, [%4];"
        : "=r"(r[0]), "=r"(r[1]), "=r"(r[2]), "=r"(r[3]) : "r"(addr));
}
__device__ __forceinline__ void ldsm_x4t(uint32_t r[4], uint32_t addr) {
    asm volatile("ldmatrix.sync.aligned.m8n8.x4.trans.shared.b16 {%0,%1,%2,%3}, [%4];"
        : "=r"(r[0]), "=r"(r[1]), "=r"(r[2]), "=r"(r[3]) : "r"(addr));
}
__device__ __forceinline__ void mma_bf16(float c[4], const uint32_t a[4], uint32_t b0, uint32_t b1) {
    asm volatile("mma.sync.aligned.m16n8k16.row.col.f32.bf16.bf16.f32 "
        "{%0,%1,%2,%3}, {%4,%5,%6,%7}, {%8,%9}, {%0,%1,%2,%3};"
        : "+f"(c[0]), "+f"(c[1]), "+f"(c[2]), "+f"(c[3])
        : "r"(a[0]), "r"(a[1]), "r"(a[2]), "r"(a[3]), "r"(b0), "r"(b1));
}
#define SWZ128(b) ((b) ^ (((b) >> 3) & 0x70))
#define SWZ64(b)  ((b) ^ (((b) >> 3) & 0x30))

// =====================================================================
// Prep: build B^T (bf16 hi/lo) for k_pre.  j<256: Hw[j][k]; j>=256: W[h][k][o]
// =====================================================================
__global__ void k_prep(const float* __restrict__ Hw, const float* __restrict__ W)
{
    const int j = blockIdx.x;
    const int k = threadIdx.x;
    float v;
    if (j < 256) v = Hw[(size_t)j * IND + k];
    else {
        int jj = j - 256, h = jj >> 6, o = jj & 63;
        v = W[((size_t)h * IND + k) * OD + o];
    }
    __nv_bfloat16 hi = __float2bfloat16(v);
    __nv_bfloat16 lo = __float2bfloat16(v - __bfloat162float(hi));
    g_BT_hi[(size_t)j * IND + k] = hi;
    g_BT_lo[(size_t)j * IND + k] = lo;
}

// =====================================================================
// Kernel 1: HMMA pre-GEMM  C[8192,512] = feat[8192,256] @ BT^T
//   CTA 128x64, 8 warps (32x32), K-chunk 32 (8 chunks),
//   single-sync software pipeline (stage c+1 overlapped with compute c).
// =====================================================================
constexpr int STAGE_PRE = 24576;
constexpr int SMEM_PRE = 2 * STAGE_PRE + 128;

__global__ __launch_bounds__(256, 2) void k_pre(
    const float* __restrict__ feat, const float* __restrict__ Hb)
{
    extern __shared__ char dsm_raw[];
    char* sm = (char*)(((uintptr_t)dsm_raw + 127) & ~(uintptr_t)127);
    const uint32_t smu = smem_to_u32(sm);

    const int tid = threadIdx.x;
    const int lane = tid & 31, wid = tid >> 5;
    const int r0 = blockIdx.x * 128;
    const int j0 = blockIdx.y * 64;

    const float* A = feat + (size_t)r0 * IND;

    const int arow = tid >> 3;
    const int acol = (tid & 7) << 2;
    const int brow = tid >> 2;
    const int bk8  = (tid & 3) << 3;

    uint32_t saoff[4];
#pragma unroll
    for (int j = 0; j < 4; j++)
        saoff[j] = SWZ64((uint32_t)(arow + 32 * j) * 64 + (uint32_t)acol * 2);
    const uint32_t sboff = SWZ64((uint32_t)brow * 64 + (uint32_t)bk8 * 2);

    float4 ar[4];
    uint4 bhr, blr;

    float acc[2][4][4];
#pragma unroll
    for (int mi = 0; mi < 2; mi++)
#pragma unroll
        for (int ni = 0; ni < 4; ni++)
#pragma unroll
            for (int r = 0; r < 4; r++) acc[mi][ni][r] = 0.0f;

    const int m_w = (wid >> 1) * 32;
    const int n_w = (wid & 1) * 32;
    const int a_row_l = lane & 15;
    const int a_colb  = ((lane >> 4) << 3) * 2;
    const int b_row_l = (lane & 7) + ((lane >> 4) << 3);
    const int b_kb    = (((lane >> 3) & 1) << 4);

    // ---- prologue: stage chunk 0, prefetch chunk 1 ----
#pragma unroll
    for (int j = 0; j < 4; j++)
        ar[j] = *(const float4*)&A[(size_t)(arow + 32 * j) * IND + acol];
    bhr = *(const uint4*)&g_BT_hi[(size_t)(j0 + brow) * IND + bk8];
    blr = *(const uint4*)&g_BT_lo[(size_t)(j0 + brow) * IND + bk8];
    {
        char* buf = sm;
#pragma unroll
        for (int j = 0; j < 4; j++) {
            uint32_t h0, l0, h1, l1;
            split2(ar[j].x, ar[j].y, h0, l0);
            split2(ar[j].z, ar[j].w, h1, l1);
            *(uint2*)(buf + saoff[j])        = make_uint2(h0, h1);
            *(uint2*)(buf + 8192 + saoff[j]) = make_uint2(l0, l1);
        }
        *(uint4*)(buf + 16384 + sboff) = bhr;
        *(uint4*)(buf + 20480 + sboff) = blr;
    }
#pragma unroll
    for (int j = 0; j < 4; j++)
        ar[j] = *(const float4*)&A[(size_t)(arow + 32 * j) * IND + 32 + acol];
    bhr = *(const uint4*)&g_BT_hi[(size_t)(j0 + brow) * IND + 32 + bk8];
    blr = *(const uint4*)&g_BT_lo[(size_t)(j0 + brow) * IND + 32 + bk8];

    for (int c = 0; c < 8; c++) {
        __syncthreads();
        // stage chunk c+1 (overlaps with compute of chunk c)
        if (c < 7) {
            char* buf = sm + ((c + 1) & 1) * STAGE_PRE;
#pragma unroll
            for (int j = 0; j < 4; j++) {
                uint32_t h0, l0, h1, l1;
                split2(ar[j].x, ar[j].y, h0, l0);
                split2(ar[j].z, ar[j].w, h1, l1);
                *(uint2*)(buf + saoff[j])        = make_uint2(h0, h1);
                *(uint2*)(buf + 8192 + saoff[j]) = make_uint2(l0, l1);
            }
            *(uint4*)(buf + 16384 + sboff) = bhr;
            *(uint4*)(buf + 20480 + sboff) = blr;
        }
        // prefetch chunk c+2
        if (c < 6) {
            const int kn = (c + 2) * 32;
#pragma unroll
            for (int j = 0; j < 4; j++)
                ar[j] = *(const float4*)&A[(size_t)(arow + 32 * j) * IND + kn + acol];
            bhr = *(const uint4*)&g_BT_hi[(size_t)(j0 + brow) * IND + kn + bk8];
            blr = *(const uint4*)&g_BT_lo[(size_t)(j0 + brow) * IND + kn + bk8];
        }

        // compute chunk c
        const uint32_t bufu = smu + (c & 1) * STAGE_PRE;
#pragma unroll
        for (int ks = 0; ks < 2; ks++) {
            uint32_t ah[2][4], al[2][4], bhf[2][4], blf[2][4];
#pragma unroll
            for (int mi = 0; mi < 2; mi++) {
                uint32_t sw = SWZ64((uint32_t)(m_w + mi * 16 + a_row_l) * 64 + (uint32_t)(ks * 32) + a_colb);
                ldsm_x4(ah[mi], bufu + sw);
                ldsm_x4(al[mi], bufu + 8192 + sw);
            }
#pragma unroll
            for (int nj = 0; nj < 2; nj++) {
                uint32_t sw = SWZ64((uint32_t)(n_w + nj * 16 + b_row_l) * 64 + (uint32_t)(ks * 32) + b_kb);
                ldsm_x4(bhf[nj], bufu + 16384 + sw);
                ldsm_x4(blf[nj], bufu + 20480 + sw);
            }
#pragma unroll
            for (int mi = 0; mi < 2; mi++)
#pragma unroll
                for (int ni = 0; ni < 4; ni++) {
                    const int j = ni >> 1, p = (ni & 1) << 1;
                    mma_bf16(acc[mi][ni], ah[mi], bhf[j][p], bhf[j][p + 1]);
                    mma_bf16(acc[mi][ni], ah[mi], blf[j][p], blf[j][p + 1]);
                    mma_bf16(acc[mi][ni], al[mi], bhf[j][p], bhf[j][p + 1]);
                }
        }
    }

    const bool is_gate = (j0 < 256);
#pragma unroll
    for (int mi = 0; mi < 2; mi++) {
#pragma unroll
        for (int rr = 0; rr < 2; rr++) {
            const int m = r0 + m_w + mi * 16 + (lane >> 2) + rr * 8;
#pragma unroll
            for (int ni = 0; ni < 4; ni++) {
                const int j = j0 + n_w + ni * 8 + ((lane & 3) << 1);
                float v0 = acc[mi][ni][rr * 2 + 0];
                float v1 = acc[mi][ni][rr * 2 + 1];
                if (is_gate) {
                    v0 = 1.0f / (1.0f + expf(-(v0 + __ldg(&Hb[j]))));
                    v1 = 1.0f / (1.0f + expf(-(v1 + __ldg(&Hb[j + 1]))));
                }
                *(float2*)&g_pre[(size_t)m * 512 + j] = make_float2(v0, v1);
            }
        }
    }
}

// =====================================================================
// Kernel 2: HMMA main GEMM per (b,h): C[2048,64] = IB @ h
//   R4 tile structure (CTA 128x64, warp 32x32, K-chunk 32, 2 CTAs/SM)
//   + single-sync software pipeline: stage(c+1) and LDG(c+2) overlap
//   with compute(c). IB write-through copy fused. elu/gate epilogue.
// =====================================================================
constexpr int STAGE_M = 24576;
constexpr int SMEM_MAIN = 2 * STAGE_M + 128;

__global__ __launch_bounds__(256, 2) void k_main_mma(
    const float* __restrict__ IB, const float* __restrict__ feat,
    const float* __restrict__ bias, float* __restrict__ out)
{
    extern __shared__ char dsm_raw[];
    char* sm = (char*)(((uintptr_t)dsm_raw + 127) & ~(uintptr_t)127);
    const uint32_t smu = smem_to_u32(sm);

    const int tid = threadIdx.x;
    const int lane = tid & 31, wid = tid >> 5;
    const int r0 = blockIdx.x * 128;
    const int bh = blockIdx.y, bb = bh >> 2, hh = bh & 3;

    const float* A   = IB + (size_t)bh * NN * NN + (size_t)r0 * NN;
    float* Acopy     = out + OUT_ELEMS + (size_t)bh * NN * NN + (size_t)r0 * NN;
    const float* Bsrc = g_pre + (size_t)bb * NN * 512 + 256 + hh * 64;  // [k][o] stride 512

    const int arow = tid >> 3;           // 0..31, rows arow+32j, j<4
    const int acol = (tid & 7) << 2;     // fp32 col 0..28
    const int brow = tid >> 3;           // 0..31 (k rows)
    const int bcol = (tid & 7) << 3;     // fp32 o col base

    uint32_t saoff[4];
#pragma unroll
    for (int j = 0; j < 4; j++)
        saoff[j] = SWZ64((uint32_t)(arow + 32 * j) * 64 + (uint32_t)acol * 2);
    const uint32_t sboff = SWZ128((uint32_t)brow * 128 + (uint32_t)bcol * 2);

    float4 ar[4], br[2];

    float acc[2][4][4];
#pragma unroll
    for (int mi = 0; mi < 2; mi++)
#pragma unroll
        for (int ni = 0; ni < 4; ni++)
#pragma unroll
            for (int r = 0; r < 4; r++) acc[mi][ni][r] = 0.0f;

    const int m_w = (wid >> 1) * 32;
    const int n_w = (wid & 1) * 32;
    const int a_row_l = lane & 15;
    const int a_colb  = ((lane >> 4) << 3) * 2;
    const int b_krow  = (lane & 7) + ((lane >> 3) & 1) * 8;
    const int b_ncol  = (lane >> 4) << 3;

    // ---- prologue: stage chunk 0 (with write-through), prefetch chunk 1 ----
#pragma unroll
    for (int j = 0; j < 4; j++)
        ar[j] = *(const float4*)&A[(size_t)(arow + 32 * j) * NN + acol];
    br[0] = *(const float4*)&Bsrc[(size_t)brow * 512 + bcol];
    br[1] = *(const float4*)&Bsrc[(size_t)brow * 512 + bcol + 4];
    {
        char* buf = sm;
#pragma unroll
        for (int j = 0; j < 4; j++) {
            *(float4*)&Acopy[(size_t)(arow + 32 * j) * NN + acol] = ar[j];
            uint32_t h0, l0, h1, l1;
            split2(ar[j].x, ar[j].y, h0, l0);
            split2(ar[j].z, ar[j].w, h1, l1);
            *(uint2*)(buf + saoff[j])        = make_uint2(h0, h1);
            *(uint2*)(buf + 8192 + saoff[j]) = make_uint2(l0, l1);
        }
        uint32_t h0, l0, h1, l1, h2, l2, h3, l3;
        split2(br[0].x, br[0].y, h0, l0);
        split2(br[0].z, br[0].w, h1, l1);
        split2(br[1].x, br[1].y, h2, l2);
        split2(br[1].z, br[1].w, h3, l3);
        *(uint4*)(buf + 16384 + sboff) = make_uint4(h0, h1, h2, h3);
        *(uint4*)(buf + 20480 + sboff) = make_uint4(l0, l1, l2, l3);
    }
#pragma unroll
    for (int j = 0; j < 4; j++)
        ar[j] = *(const float4*)&A[(size_t)(arow + 32 * j) * NN + 32 + acol];
    br[0] = *(const float4*)&Bsrc[(size_t)(32 + brow) * 512 + bcol];
    br[1] = *(const float4*)&Bsrc[(size_t)(32 + brow) * 512 + bcol + 4];

    for (int c = 0; c < 64; c++) {
        __syncthreads();

        // stage chunk c+1 (write-through STG + split STS) — overlaps compute(c)
        if (c < 63) {
            char* buf = sm + ((c + 1) & 1) * STAGE_M;
            const int k1 = (c + 1) * 32;
#pragma unroll
            for (int j = 0; j < 4; j++) {
                *(float4*)&Acopy[(size_t)(arow + 32 * j) * NN + k1 + acol] = ar[j];
                uint32_t h0, l0, h1, l1;
                split2(ar[j].x, ar[j].y, h0, l0);
                split2(ar[j].z, ar[j].w, h1, l1);
                *(uint2*)(buf + saoff[j])        = make_uint2(h0, h1);
                *(uint2*)(buf + 8192 + saoff[j]) = make_uint2(l0, l1);
            }
            uint32_t h0, l0, h1, l1, h2, l2, h3, l3;
            split2(br[0].x, br[0].y, h0, l0);
            split2(br[0].z, br[0].w, h1, l1);
            split2(br[1].x, br[1].y, h2, l2);
            split2(br[1].z, br[1].w, h3, l3);
            *(uint4*)(buf + 16384 + sboff) = make_uint4(h0, h1, h2, h3);
            *(uint4*)(buf + 20480 + sboff) = make_uint4(l0, l1, l2, l3);
        }
        // prefetch chunk c+2
        if (c < 62) {
            const int kn = (c + 2) * 32;
#pragma unroll
            for (int j = 0; j < 4; j++)
                ar[j] = *(const float4*)&A[(size_t)(arow + 32 * j) * NN + kn + acol];
            br[0] = *(const float4*)&Bsrc[(size_t)(kn + brow) * 512 + bcol];
            br[1] = *(const float4*)&Bsrc[(size_t)(kn + brow) * 512 + bcol + 4];
        }

        // compute chunk c
        const uint32_t bufu = smu + (c & 1) * STAGE_M;
#pragma unroll
        for (int ks = 0; ks < 2; ks++) {
            uint32_t ah[2][4], al[2][4], bhf[2][4], blf[2][4];
#pragma unroll
            for (int mi = 0; mi < 2; mi++) {
                uint32_t sw = SWZ64((uint32_t)(m_w + mi * 16 + a_row_l) * 64 + (uint32_t)(ks * 32) + a_colb);
                ldsm_x4(ah[mi], bufu + sw);
                ldsm_x4(al[mi], bufu + 8192 + sw);
            }
#pragma unroll
            for (int nj = 0; nj < 2; nj++) {
                uint32_t sw = SWZ128((uint32_t)(ks * 16 + b_krow) * 128 + (uint32_t)(n_w + nj * 16 + b_ncol) * 2);
                ldsm_x4t(bhf[nj], bufu + 16384 + sw);
                ldsm_x4t(blf[nj], bufu + 20480 + sw);
            }
#pragma unroll
            for (int mi = 0; mi < 2; mi++)
#pragma unroll
                for (int ni = 0; ni < 4; ni++) {
                    const int j = ni >> 1, p = (ni & 1) << 1;
                    mma_bf16(acc[mi][ni], ah[mi], bhf[j][p], bhf[j][p + 1]);
                    mma_bf16(acc[mi][ni], ah[mi], blf[j][p], blf[j][p + 1]);
                    mma_bf16(acc[mi][ni], al[mi], bhf[j][p], bhf[j][p + 1]);
                }
        }
    }

    // epilogue: bias + elu + sigmoid-gate blend
#pragma unroll
    for (int mi = 0; mi < 2; mi++) {
#pragma unroll
        for (int rr = 0; rr < 2; rr++) {
            const int nrow = r0 + m_w + mi * 16 + (lane >> 2) + rr * 8;
            const size_t row = (size_t)bb * NN + nrow;
#pragma unroll
            for (int ni = 0; ni < 4; ni++) {
                const int col = n_w + ni * 8 + ((lane & 3) << 1);
                const int cg = hh * 64 + col;
                float v0 = acc[mi][ni][rr * 2 + 0] + __ldg(&bias[col]);
                float v1 = acc[mi][ni][rr * 2 + 1] + __ldg(&bias[col + 1]);
                float e0 = (v0 > 0.0f) ? v0 : expm1f(v0);
                float e1 = (v1 > 0.0f) ? v1 : expm1f(v1);
                float2 g2 = *(const float2*)&g_pre[row * 512 + cg];
                float2 f2 = *(const float2*)&feat[row * IND + cg];
                float2 o2;
                o2.x = g2.x * e0 + (1.0f - g2.x) * f2.x;
                o2.y = g2.y * e1 + (1.0f - g2.y) * f2.y;
                *(float2*)&out[row * IND + cg] = o2;
            }
        }
    }
}

extern "C" void kernel_launch(void* const* d_in, const int* in_sizes, int n_in,
                              void* d_out, int out_size)
{
    const float* feat = (const float*)d_in[0];  // [4,2048,256]
    const float* IB   = (const float*)d_in[1];  // [4,4,2048,2048]
    const float* W    = (const float*)d_in[2];  // [4,256,64]
    const float* bias = (const float*)d_in[3];  // [64]
    const float* Hw   = (const float*)d_in[4];  // [256,256]
    const float* Hb   = (const float*)d_in[5];  // [256]
    float* out = (float*)d_out;

    // Prep: bf16 hi/lo B^T for k_pre
    k_prep<<<512, 256>>>(Hw, W);

    // Kernel 1: gate + h (HMMA, pipelined)
    cudaFuncSetAttribute(k_pre, cudaFuncAttributeMaxDynamicSharedMemorySize, SMEM_PRE);
    dim3 g1(NB * NN / 128, 512 / 64);
    k_pre<<<g1, 256, SMEM_PRE>>>(feat, Hb);

    // Kernel 2: HMMA main GEMM (pipelined) + IB copy + fused epilogue
    cudaFuncSetAttribute(k_main_mma, cudaFuncAttributeMaxDynamicSharedMemorySize, SMEM_MAIN);
    dim3 g2(NN / 128, NB * NH);
    k_main_mma<<<g2, 256, SMEM_MAIN>>>(IB, feat, bias, out);
}